// round 10
// baseline (speedup 1.0000x reference)
#include <cuda_runtime.h>
#include <cuda_bf16.h>
#include <math.h>
#include <stdint.h>

// Problem constants (fixed by the dataset)
#define B_  4
#define Q_  1024
#define D_  1024
#define N_  16
#define DH_ 64
#define DI_ 4096
#define BQ  (B_ * Q_)      // 4096
#define D3  (3 * D_)       // 3072

// ---------------- scratch (static device globals; no allocation) -------------
__device__ float g_heads[BQ * D3];   // 48 MB
__device__ float g_rk   [Q_ * D_];   //  4 MB
__device__ float g_av   [BQ * D_];   // 16 MB
__device__ float g_tmp  [BQ * D_];   // 16 MB
__device__ float g_out1 [BQ * D_];   // 16 MB
__device__ float g_ff1  [BQ * DI_];  // 64 MB

// fragment-major tf32 operand buffers (prep pass outputs)
__device__ uint32_t g_qkvw_p[384 * 128 * 64];   // B-frag: N=3072, K=1024
__device__ uint32_t g_rw_p  [128 * 128 * 64];   // B-frag: 1024x1024
__device__ uint32_t g_ow_p  [128 * 128 * 64];   // B-frag: 1024x1024
__device__ uint32_t g_f1w_p [512 * 128 * 64];   // B-frag: N=4096, K=1024
__device__ uint32_t g_f2w_p [128 * 512 * 64];   // B-frag: N=1024, K=4096
__device__ uint32_t g_w_p   [256 * 128 * 128];  // A-frag: M=4096, K=1024
__device__ uint32_t g_r_p   [ 64 * 128 * 128];  // A-frag: M=1024, K=1024

// ---------------- helpers ------------------------------------------------------
__device__ __forceinline__ uint32_t f2tf32(float x) {
    uint32_t r;
    asm("cvt.rna.tf32.f32 %0, %1;" : "=r"(r) : "f"(x));
    return r;
}
__device__ __forceinline__ void mma_tf32(float* d, const uint32_t* a,
                                         const uint32_t* b) {
    asm volatile(
        "mma.sync.aligned.m16n8k8.row.col.f32.tf32.tf32.f32 "
        "{%0,%1,%2,%3}, {%4,%5,%6,%7}, {%8,%9}, {%0,%1,%2,%3};"
        : "+f"(d[0]), "+f"(d[1]), "+f"(d[2]), "+f"(d[3])
        : "r"(a[0]), "r"(a[1]), "r"(a[2]), "r"(a[3]), "r"(b[0]), "r"(b[1]));
}
__device__ __forceinline__ uint32_t smem_u32(const void* p) {
    uint32_t a;
    asm("{ .reg .u64 t; cvta.to.shared.u64 t, %1; cvt.u32.u64 %0, t; }"
        : "=r"(a) : "l"(p));
    return a;
}
__device__ __forceinline__ void cpa16(uint32_t dst, const void* src) {
    asm volatile("cp.async.cg.shared.global [%0], [%1], 16;"
                 :: "r"(dst), "l"(src));
}
#define CP_COMMIT() asm volatile("cp.async.commit_group;" ::: "memory")
#define CP_WAIT0()  asm volatile("cp.async.wait_group 0;" ::: "memory")

// A-fragment word within a CTA chunk (16 k x 128 rows), 8 mtiles per ktile.
__device__ __forceinline__ int a_word(int row, int k) {
    int ld = ((row & 7) << 2) | (k & 3);
    int e  = ((k & 4) >> 1) | ((row & 8) >> 3);
    int f  = ld ^ (ld >> 3);
    return (((k >> 3) << 3) | (row >> 4)) * 128 + f * 4 + e;
}

// ---------------- prep kernels: fp32 row-major -> tf32 fragment-major ---------
// B-frag: tile = kt*(N/8)+nt, 64 words; word h*2+e; inverse: ld=h^(h>>3),
//   n = nt*8+(ld>>2), k = kt*8+(ld&3)+e*4.
__global__ void __launch_bounds__(256) prep_b(
    const float* __restrict__ W, uint32_t* __restrict__ out, int N, int K)
{
    const int t    = blockIdx.x * 256 + threadIdx.x;
    const int h    = t & 31;
    const int tile = t >> 5;
    const int nt8  = N >> 3;
    const int kt   = tile / nt8;
    if (kt >= (K >> 3)) return;
    const int nt = tile - kt * nt8;
    const int ld = h ^ (h >> 3);
    const int n  = nt * 8 + (ld >> 2);
    const int k  = kt * 8 + (ld & 3);
    uint2 v;
    v.x = f2tf32(W[(size_t)n * K + k]);
    v.y = f2tf32(W[(size_t)n * K + k + 4]);
    *(uint2*)&out[(size_t)tile * 64 + h * 2] = v;
}

// A-frag: tile = kt*(M/16)+mt, 128 words; word f*4+e; inverse: ld=f^(f>>3),
//   m = mt*16+(e&1)*8+(ld>>2), k = kt*8+(e>>1)*4+(ld&3).
__global__ void __launch_bounds__(256) prep_a(
    const float* __restrict__ A, uint32_t* __restrict__ out, int M, int K)
{
    const int t    = blockIdx.x * 256 + threadIdx.x;
    const int f    = t & 31;
    const int tile = t >> 5;
    const int mt16 = M >> 4;
    const int kt   = tile / mt16;
    if (kt >= (K >> 3)) return;
    const int mt = tile - kt * mt16;
    const int ld = f ^ (f >> 3);
    const int mb = mt * 16 + (ld >> 2);
    const int kb = kt * 8 + (ld & 3);
    uint4 v;
    v.x = f2tf32(A[(size_t)mb * K + kb]);
    v.y = f2tf32(A[(size_t)(mb + 8) * K + kb]);
    v.z = f2tf32(A[(size_t)mb * K + kb + 4]);
    v.w = f2tf32(A[(size_t)(mb + 8) * K + kb + 4]);
    *(uint4*)&out[(size_t)tile * 128 + f * 4] = v;
}

// ---------------- HMMA GEMM: C = A[M,K] @ W[N,K]^T (+bias)(+relu) -------------
// 128x128 CTA tile, BK=16, 8 warps (4x2), warp tile 32x64.
// B always cp.async from fragment-major prep buffer. A either cp.async from
// prep buffer (APREP) or LDG+cvt+STS scatter.
template<bool APREP, bool BIAS, bool RELU>
__global__ void __launch_bounds__(256, 2) gemm_cp(
    const float* __restrict__ A, const uint32_t* __restrict__ Ap,
    const uint32_t* __restrict__ Bp, const float* __restrict__ bias,
    float* __restrict__ C, int M, int K, int ldc)
{
    __shared__ uint32_t sA[2][2048];
    __shared__ uint32_t sB[2][2048];

    const int t    = threadIdx.x;
    const int lane = t & 31;
    const int w    = t >> 5;
    const int g    = lane >> 2;
    const int t4   = lane & 3;
    const int fl   = lane ^ (lane >> 3);
    const int m0   = blockIdx.y * 128;
    const int n0   = blockIdx.x * 128;
    const int wm   = (w >> 1) * 32;
    const int wn   = (w & 1) * 64;
    const int mt0  = (w >> 1) * 2;
    const int nt0  = (w & 1) * 8;
    const int lrow = t >> 1;
    const int lkq  = (t & 1) * 8;
    const int NC   = K >> 4;
    const int nt8  = ldc >> 3;
    const int mt16 = M >> 4;

    const uint32_t sAb = smem_u32(sA);
    const uint32_t sBb = smem_u32(sB);

    float acc[2][8][4];
    #pragma unroll
    for (int mt = 0; mt < 2; mt++)
        #pragma unroll
        for (int nt = 0; nt < 8; nt++)
            #pragma unroll
            for (int e = 0; e < 4; e++) acc[mt][nt][e] = 0.f;

    auto issue = [&](int bf, int c) {
        #pragma unroll
        for (int kk = 0; kk < 2; kk++) {
            const uint32_t* bsrc =
                Bp + ((size_t)(2 * c + kk) * nt8 + (n0 >> 3)) * 64 + t * 4;
            cpa16(sBb + bf * 8192 + kk * 4096 + t * 16, bsrc);
        }
        if (APREP) {
            #pragma unroll
            for (int kk = 0; kk < 2; kk++) {
                const uint32_t* asrc =
                    Ap + ((size_t)(2 * c + kk) * mt16 + (m0 >> 4)) * 128 + t * 4;
                cpa16(sAb + bf * 8192 + kk * 4096 + t * 16, asrc);
            }
        }
    };
    auto ldA = [&](int c, float4& p0, float4& p1) {
        const float* ap = A + (size_t)(m0 + lrow) * K + c * 16 + lkq;
        p0 = *(const float4*)ap;
        p1 = *(const float4*)(ap + 4);
    };
    auto stsA = [&](int bf, float4 p0, float4 p1) {
        float va[8] = {p0.x, p0.y, p0.z, p0.w, p1.x, p1.y, p1.z, p1.w};
        #pragma unroll
        for (int u = 0; u < 8; u++)
            sA[bf][a_word(lrow, lkq + u)] = f2tf32(va[u]);
    };

    // ---- prologue: chunk 0 ----
    float4 pa0, pa1;
    issue(0, 0);
    CP_COMMIT();
    if (!APREP) { ldA(0, pa0, pa1); stsA(0, pa0, pa1); }
    CP_WAIT0();
    __syncthreads();

    int buf = 0;
    for (int c = 0; c < NC; c++) {
        const bool hn = (c + 1 < NC);
        if (hn) {
            issue(buf ^ 1, c + 1);
            CP_COMMIT();
            if (!APREP) ldA(c + 1, pa0, pa1);
        }

        #pragma unroll
        for (int kk = 0; kk < 2; kk++) {
            uint4 af[2];
            uint2 bf[8];
            #pragma unroll
            for (int mt = 0; mt < 2; mt++)
                af[mt] = *(const uint4*)&sA[buf][(kk * 8 + mt0 + mt) * 128 + fl * 4];
            #pragma unroll
            for (int nt = 0; nt < 8; nt++)
                bf[nt] = *(const uint2*)&sB[buf][(kk * 16 + nt0 + nt) * 64 + fl * 2];
            #pragma unroll
            for (int mt = 0; mt < 2; mt++)
                #pragma unroll
                for (int nt = 0; nt < 8; nt++)
                    mma_tf32(acc[mt][nt], (const uint32_t*)&af[mt],
                             (const uint32_t*)&bf[nt]);
        }

        if (hn) {
            if (!APREP) stsA(buf ^ 1, pa0, pa1);
            CP_WAIT0();
            __syncthreads();
            buf ^= 1;
        }
    }

    // ---- epilogue ----
    #pragma unroll
    for (int mt = 0; mt < 2; mt++) {
        const int row = m0 + wm + mt * 16 + g;
        #pragma unroll
        for (int nt = 0; nt < 8; nt++) {
            const int col = n0 + wn + nt * 8 + 2 * t4;
            float b0v = BIAS ? bias[col]     : 0.f;
            float b1v = BIAS ? bias[col + 1] : 0.f;
            float x0 = acc[mt][nt][0] + b0v;
            float x1 = acc[mt][nt][1] + b1v;
            float x2 = acc[mt][nt][2] + b0v;
            float x3 = acc[mt][nt][3] + b1v;
            if (RELU) {
                x0 = fmaxf(x0, 0.f); x1 = fmaxf(x1, 0.f);
                x2 = fmaxf(x2, 0.f); x3 = fmaxf(x3, 0.f);
            }
            *(float2*)&C[(size_t)row * ldc + col]       = make_float2(x0, x1);
            *(float2*)&C[(size_t)(row + 8) * ldc + col] = make_float2(x2, x3);
        }
    }
}

// ---------------- MMA flash attention (R8, unchanged) --------------------------
__device__ __forceinline__ int bw8(int nn, int k) {
    int ld = ((nn & 7) << 2) | (k & 3);
    int e  = (k & 4) >> 2;
    int h  = ld ^ (ld >> 3);
    return ((k >> 3) * 8 + (nn >> 3)) * 72 + h * 2 + e;
}
__device__ __forceinline__ int bw16(int nn, int k) {
    int ld = ((nn & 7) << 2) | (k & 3);
    int e  = (k & 4) >> 2;
    int h  = ld ^ (ld >> 3);
    return ((k >> 3) * 16 + (nn >> 3)) * 72 + h * 2 + e;
}
__device__ __forceinline__ int aw4(int row, int k) {
    int ld = ((row & 7) << 2) | (k & 3);
    int e  = ((k & 4) >> 1) | ((row & 8) >> 3);
    int f  = ld ^ (ld >> 3);
    return ((k >> 3) * 4 + (row >> 4)) * 128 + f * 4 + e;
}

#define ATT_WORDS (4608 + 4608 + 9216 + 8448 + 256)
#define ATT_SMEM  (ATT_WORDS * 4)

__global__ void __launch_bounds__(256, 1) attn_mma(
    const float* __restrict__ heads, const float* __restrict__ rk,
    const float* __restrict__ rwb, const float* __restrict__ rrb,
    float* __restrict__ av)
{
    extern __shared__ uint32_t smw[];
    uint32_t* sK  = smw;
    uint32_t* sV  = sK + 4608;
    uint32_t* sB  = sV + 4608;
    float*    sBD = (float*)(sB + 9216);
    uint32_t* sP  = (uint32_t*)sBD;
    float*    red = sBD + 8448;

    const int i0   = (gridDim.x - 1 - blockIdx.x) * 64;
    const int n    = blockIdx.y;
    const int b    = blockIdx.z;
    const int t    = threadIdx.x;
    const int lane = t & 31;
    const int w    = t >> 5;
    const int wr   = w & 3;
    const int wc   = w >> 2;
    const int g    = lane >> 2;
    const int t4   = lane & 3;
    const int fl   = lane ^ (lane >> 3);

    uint32_t qw[8][4], qr[8][4];
    {
        const float* qb = heads + (size_t)(b * Q_ + i0 + wr * 16 + g) * D3 + n * DH_;
        const float* wb = rwb + n * DH_;
        const float* rb = rrb + n * DH_;
        #pragma unroll
        for (int kt = 0; kt < 8; kt++) {
            const int c0 = kt * 8 + t4, c1 = c0 + 4;
            float q00 = qb[c0], q01 = qb[c1];
            float q10 = qb[8 * D3 + c0], q11 = qb[8 * D3 + c1];
            qw[kt][0] = f2tf32(q00 + wb[c0]);
            qw[kt][1] = f2tf32(q10 + wb[c0]);
            qw[kt][2] = f2tf32(q01 + wb[c1]);
            qw[kt][3] = f2tf32(q11 + wb[c1]);
            qr[kt][0] = f2tf32(q00 + rb[c0]);
            qr[kt][1] = f2tf32(q10 + rb[c0]);
            qr[kt][2] = f2tf32(q01 + rb[c1]);
            qr[kt][3] = f2tf32(q11 + rb[c1]);
        }
    }

    float O[4][4];
    #pragma unroll
    for (int nt = 0; nt < 4; nt++)
        #pragma unroll
        for (int e = 0; e < 4; e++) O[nt][e] = 0.f;
    float m0r = -1e30f, m1r = -1e30f, l0r = 0.f, l1r = 0.f;

    const int di0 = wr * 16 + g;
    const int di1 = di0 + 8;

    for (int j0 = 0; j0 <= i0; j0 += 64) {
        __syncthreads();

        {
            const int jrow = t >> 2, d0 = (t & 3) * 16;
            const float* kp = heads + (size_t)(b * Q_ + j0 + jrow) * D3 + D_ + n * DH_ + d0;
            const float* vp = kp + D_;
            #pragma unroll
            for (int u = 0; u < 16; u += 4) {
                float4 kv = *(const float4*)(kp + u);
                float4 vv = *(const float4*)(vp + u);
                const int d = d0 + u;
                sK[bw8(jrow, d + 0)] = f2tf32(kv.x);
                sK[bw8(jrow, d + 1)] = f2tf32(kv.y);
                sK[bw8(jrow, d + 2)] = f2tf32(kv.z);
                sK[bw8(jrow, d + 3)] = f2tf32(kv.w);
                sV[bw8(d + 0, jrow)] = f2tf32(vv.x);
                sV[bw8(d + 1, jrow)] = f2tf32(vv.y);
                sV[bw8(d + 2, jrow)] = f2tf32(vv.z);
                sV[bw8(d + 3, jrow)] = f2tf32(vv.w);
            }
        }
        {
            const int lr_ = t >> 1, d0 = (t & 1) * 32;
            int grow = (Q_ - 64 - i0 + j0) + lr_;
            if (grow > Q_ - 1) grow = Q_ - 1;
            const float* rp = rk + (size_t)grow * D_ + n * DH_ + d0;
            #pragma unroll
            for (int u = 0; u < 32; u += 4) {
                float4 rv = *(const float4*)(rp + u);
                const int d = d0 + u;
                sB[bw16(lr_, d + 0)] = f2tf32(rv.x);
                sB[bw16(lr_, d + 1)] = f2tf32(rv.y);
                sB[bw16(lr_, d + 2)] = f2tf32(rv.z);
                sB[bw16(lr_, d + 3)] = f2tf32(rv.w);
            }
        }
        __syncthreads();

        {
            float bd[8][4];
            #pragma unroll
            for (int nt = 0; nt < 8; nt++)
                #pragma unroll
                for (int e = 0; e < 4; e++) bd[nt][e] = 0.f;
            #pragma unroll
            for (int kt = 0; kt < 8; kt++) {
                uint2 bf[8];
                #pragma unroll
                for (int nt = 0; nt < 8; nt++)
                    bf[nt] = *(const uint2*)&sB[(kt * 16 + wc * 8 + nt) * 72 + fl * 2];
                #pragma unroll
                for (int nt = 0; nt < 8; nt++)
                    mma_tf32(bd[nt], qr[kt], (const uint32_t*)&bf[nt]);
            }
            #pragma unroll
            for (int nt = 0; nt < 8; nt++) {
                const int lc = wc * 64 + nt * 8 + 2 * t4;
                sBD[di0 * 132 + lc]     = bd[nt][0];
                sBD[di0 * 132 + lc + 1] = bd[nt][1];
                sBD[di1 * 132 + lc]     = bd[nt][2];
                sBD[di1 * 132 + lc + 1] = bd[nt][3];
            }
        }
        __syncthreads();

        float p[4][4];
        {
            float ac[4][4];
            #pragma unroll
            for (int nt = 0; nt < 4; nt++)
                #pragma unroll
                for (int e = 0; e < 4; e++) ac[nt][e] = 0.f;
            #pragma unroll
            for (int kt = 0; kt < 8; kt++) {
                uint2 kf[4];
                #pragma unroll
                for (int nt = 0; nt < 4; nt++)
                    kf[nt] = *(const uint2*)&sK[(kt * 8 + wc * 4 + nt) * 72 + fl * 2];
                #pragma unroll
                for (int nt = 0; nt < 4; nt++)
                    mma_tf32(ac[nt], qw[kt], (const uint32_t*)&kf[nt]);
            }
            const bool diag = (j0 == i0);
            #pragma unroll
            for (int nt = 0; nt < 4; nt++) {
                const int dj = wc * 32 + nt * 8 + 2 * t4;
                float v00 = (ac[nt][0] + sBD[di0 * 132 + 63 - di0 + dj])     * 0.125f;
                float v01 = (ac[nt][1] + sBD[di0 * 132 + 63 - di0 + dj + 1]) * 0.125f;
                float v10 = (ac[nt][2] + sBD[di1 * 132 + 63 - di1 + dj])     * 0.125f;
                float v11 = (ac[nt][3] + sBD[di1 * 132 + 63 - di1 + dj + 1]) * 0.125f;
                if (diag) {
                    if (dj     > di0) v00 = -1e30f;
                    if (dj + 1 > di0) v01 = -1e30f;
                    if (dj     > di1) v10 = -1e30f;
                    if (dj + 1 > di1) v11 = -1e30f;
                }
                p[nt][0] = v00; p[nt][1] = v01; p[nt][2] = v10; p[nt][3] = v11;
            }
        }

        {
            float mx0 = -1e30f, mx1 = -1e30f;
            #pragma unroll
            for (int nt = 0; nt < 4; nt++) {
                mx0 = fmaxf(mx0, fmaxf(p[nt][0], p[nt][1]));
                mx1 = fmaxf(mx1, fmaxf(p[nt][2], p[nt][3]));
            }
            mx0 = fmaxf(mx0, __shfl_xor_sync(0xffffffffu, mx0, 1));
            mx0 = fmaxf(mx0, __shfl_xor_sync(0xffffffffu, mx0, 2));
            mx1 = fmaxf(mx1, __shfl_xor_sync(0xffffffffu, mx1, 1));
            mx1 = fmaxf(mx1, __shfl_xor_sync(0xffffffffu, mx1, 2));
            if (t4 == 0) {
                red[wc * 64 + di0] = mx0;
                red[wc * 64 + di1] = mx1;
            }
        }
        __syncthreads();

        const float mn0 = fmaxf(m0r, fmaxf(red[di0], red[64 + di0]));
        const float mn1 = fmaxf(m1r, fmaxf(red[di1], red[64 + di1]));
        const float fac0 = __expf(m0r - mn0);
        const float fac1 = __expf(m1r - mn1);
        m0r = mn0; m1r = mn1;

        {
            float s0 = 0.f, s1 = 0.f;
            #pragma unroll
            for (int nt = 0; nt < 4; nt++) {
                p[nt][0] = __expf(p[nt][0] - mn0);
                p[nt][1] = __expf(p[nt][1] - mn0);
                p[nt][2] = __expf(p[nt][2] - mn1);
                p[nt][3] = __expf(p[nt][3] - mn1);
                s0 += p[nt][0] + p[nt][1];
                s1 += p[nt][2] + p[nt][3];
            }
            s0 += __shfl_xor_sync(0xffffffffu, s0, 1);
            s0 += __shfl_xor_sync(0xffffffffu, s0, 2);
            s1 += __shfl_xor_sync(0xffffffffu, s1, 1);
            s1 += __shfl_xor_sync(0xffffffffu, s1, 2);
            if (t4 == 0) {
                red[128 + wc * 64 + di0] = s0;
                red[128 + wc * 64 + di1] = s1;
            }
        }
        __syncthreads();

        l0r = l0r * fac0 + red[128 + di0] + red[128 + 64 + di0];
        l1r = l1r * fac1 + red[128 + di1] + red[128 + 64 + di1];
        #pragma unroll
        for (int nt = 0; nt < 4; nt++) {
            O[nt][0] *= fac0; O[nt][1] *= fac0;
            O[nt][2] *= fac1; O[nt][3] *= fac1;
        }

        #pragma unroll
        for (int nt = 0; nt < 4; nt++) {
            const int dj = wc * 32 + nt * 8 + 2 * t4;
            sP[aw4(di0, dj)]     = f2tf32(p[nt][0]);
            sP[aw4(di0, dj + 1)] = f2tf32(p[nt][1]);
            sP[aw4(di1, dj)]     = f2tf32(p[nt][2]);
            sP[aw4(di1, dj + 1)] = f2tf32(p[nt][3]);
        }
        __syncthreads();

        #pragma unroll
        for (int kt = 0; kt < 8; kt++) {
            uint4 af = *(const uint4*)&sP[(kt * 4 + wr) * 128 + fl * 4];
            uint2 vf[4];
            #pragma unroll
            for (int nt = 0; nt < 4; nt++)
                vf[nt] = *(const uint2*)&sV[(kt * 8 + wc * 4 + nt) * 72 + fl * 2];
            #pragma unroll
            for (int nt = 0; nt < 4; nt++)
                mma_tf32(O[nt], (const uint32_t*)&af, (const uint32_t*)&vf[nt]);
        }
    }

    const float inv0 = 1.f / l0r;
    const float inv1 = 1.f / l1r;
    #pragma unroll
    for (int nt = 0; nt < 4; nt++) {
        const int col = n * DH_ + wc * 32 + nt * 8 + 2 * t4;
        *(float2*)&av[(size_t)(b * Q_ + i0 + di0) * D_ + col] =
            make_float2(O[nt][0] * inv0, O[nt][1] * inv0);
        *(float2*)&av[(size_t)(b * Q_ + i0 + di1) * D_ + col] =
            make_float2(O[nt][2] * inv1, O[nt][3] * inv1);
    }
}

// ---------------- fused residual add + LayerNorm (row per block) -------------
__global__ void __launch_bounds__(256) add_ln_kernel(
    const float* __restrict__ x, const float* __restrict__ resid,
    const float* __restrict__ g, const float* __restrict__ bta,
    float* __restrict__ out)
{
    const int row = blockIdx.x;
    const int t = threadIdx.x;
    __shared__ float red[256];

    float v[4];
    float s = 0.f;
    #pragma unroll
    for (int u = 0; u < 4; u++) {
        int c = t + u * 256;
        v[u] = x[(size_t)row * D_ + c] + resid[(size_t)row * D_ + c];
        s += v[u];
    }
    red[t] = s;
    __syncthreads();
    for (int o = 128; o > 0; o >>= 1) {
        if (t < o) red[t] += red[t + o];
        __syncthreads();
    }
    const float mean = red[0] * (1.f / D_);
    __syncthreads();

    s = 0.f;
    #pragma unroll
    for (int u = 0; u < 4; u++) {
        float dd = v[u] - mean;
        s += dd * dd;
    }
    red[t] = s;
    __syncthreads();
    for (int o = 128; o > 0; o >>= 1) {
        if (t < o) red[t] += red[t + o];
        __syncthreads();
    }
    const float rstd = rsqrtf(red[0] * (1.f / D_) + 1e-5f);

    #pragma unroll
    for (int u = 0; u < 4; u++) {
        int c = t + u * 256;
        out[(size_t)row * D_ + c] = (v[u] - mean) * rstd * g[c] + bta[c];
    }
}

// ---------------- host launch -------------------------------------------------
extern "C" void kernel_launch(void* const* d_in, const int* in_sizes, int n_in,
                              void* d_out, int out_size)
{
    const float* w     = (const float*)d_in[0];
    const float* r     = (const float*)d_in[1];
    const float* qkv_w = (const float*)d_in[3];
    const float* r_w   = (const float*)d_in[4];
    const float* o_w   = (const float*)d_in[5];
    const float* rwb   = (const float*)d_in[6];
    const float* rrb   = (const float*)d_in[7];
    const float* ln1_g = (const float*)d_in[8];
    const float* ln1_b = (const float*)d_in[9];
    const float* ff_w1 = (const float*)d_in[10];
    const float* ff_b1 = (const float*)d_in[11];
    const float* ff_w2 = (const float*)d_in[12];
    const float* ff_b2 = (const float*)d_in[13];
    const float* ln2_g = (const float*)d_in[14];
    const float* ln2_b = (const float*)d_in[15];
    float* out = (float*)d_out;

    float *heads, *rk, *av, *tmp, *out1, *ff1;
    cudaGetSymbolAddress((void**)&heads, g_heads);
    cudaGetSymbolAddress((void**)&rk,    g_rk);
    cudaGetSymbolAddress((void**)&av,    g_av);
    cudaGetSymbolAddress((void**)&tmp,   g_tmp);
    cudaGetSymbolAddress((void**)&out1,  g_out1);
    cudaGetSymbolAddress((void**)&ff1,   g_ff1);

    uint32_t *qkvw_p, *rw_p, *ow_p, *f1w_p, *f2w_p, *w_p, *r_p;
    cudaGetSymbolAddress((void**)&qkvw_p, g_qkvw_p);
    cudaGetSymbolAddress((void**)&rw_p,   g_rw_p);
    cudaGetSymbolAddress((void**)&ow_p,   g_ow_p);
    cudaGetSymbolAddress((void**)&f1w_p,  g_f1w_p);
    cudaGetSymbolAddress((void**)&f2w_p,  g_f2w_p);
    cudaGetSymbolAddress((void**)&w_p,    g_w_p);
    cudaGetSymbolAddress((void**)&r_p,    g_r_p);

    cudaFuncSetAttribute(attn_mma,
        cudaFuncAttributeMaxDynamicSharedMemorySize, ATT_SMEM);

    // ---- prep passes (fragment-major tf32 operand buffers) ----
    prep_b<<<(384 * 128 * 32) / 256, 256>>>(qkv_w, qkvw_p, D3, D_);
    prep_b<<<(128 * 128 * 32) / 256, 256>>>(r_w,   rw_p,   D_, D_);
    prep_b<<<(128 * 128 * 32) / 256, 256>>>(o_w,   ow_p,   D_, D_);
    prep_b<<<(512 * 128 * 32) / 256, 256>>>(ff_w1, f1w_p,  DI_, D_);
    prep_b<<<(128 * 512 * 32) / 256, 256>>>(ff_w2, f2w_p,  D_, DI_);
    prep_a<<<(256 * 128 * 32) / 256, 256>>>(w, w_p, BQ, D_);
    prep_a<<<( 64 * 128 * 32) / 256, 256>>>(r, r_p, Q_, D_);

    // 1) QKV projection (A+B via cp.async)                [4096, 3072]
    gemm_cp<true, false, false><<<dim3(D3 / 128, BQ / 128), 256>>>(
        nullptr, w_p, qkvw_p, nullptr, heads, BQ, D_, D3);

    // 2) rk = r @ r_w^T                                   [1024, 1024]
    gemm_cp<true, false, false><<<dim3(D_ / 128, Q_ / 128), 256>>>(
        nullptr, r_p, rw_p, nullptr, rk, Q_, D_, D_);

    // 3) MMA flash attention                              av [4096, 1024]
    attn_mma<<<dim3(Q_ / 64, N_, B_), 256, ATT_SMEM>>>(
        heads, rk, rwb, rrb, av);

    // 4) O projection                                     [4096, 1024]
    gemm_cp<false, false, false><<<dim3(D_ / 128, BQ / 128), 256>>>(
        av, nullptr, ow_p, nullptr, tmp, BQ, D_, D_);

    // 5) out1 = LN(w + tmp)
    add_ln_kernel<<<BQ, 256>>>(tmp, w, ln1_g, ln1_b, out1);

    // 6) ff1 = relu(out1 @ ff_w1^T + b1)                  [4096, 4096]
    gemm_cp<false, true, true><<<dim3(DI_ / 128, BQ / 128), 256>>>(
        out1, nullptr, f1w_p, ff_b1, ff1, BQ, D_, DI_);

    // 7) tmp = ff1 @ ff_w2^T + b2                         [4096, 1024]
    gemm_cp<false, true, false><<<dim3(D_ / 128, BQ / 128), 256>>>(
        ff1, nullptr, f2w_p, ff_b2, tmp, BQ, DI_, D_);

    // 8) out = LN(out1 + tmp)
    add_ln_kernel<<<BQ, 256>>>(tmp, out1, ln2_g, ln2_b, out);
}

// round 11
// speedup vs baseline: 1.2212x; 1.2212x over previous
#include <cuda_runtime.h>
#include <cuda_bf16.h>
#include <math.h>
#include <stdint.h>

// Problem constants (fixed by the dataset)
#define B_  4
#define Q_  1024
#define D_  1024
#define N_  16
#define DH_ 64
#define DI_ 4096
#define BQ  (B_ * Q_)      // 4096
#define D3  (3 * D_)       // 3072

// ---------------- scratch (static device globals; no allocation) -------------
__device__ float g_heads[BQ * D3];   // 48 MB
__device__ float g_rk   [Q_ * D_];   //  4 MB
__device__ float g_av   [BQ * D_];   // 16 MB
__device__ float g_tmp  [BQ * D_];   // 16 MB
__device__ float g_out1 [BQ * D_];   // 16 MB
__device__ float g_ff1  [BQ * DI_];  // 64 MB

// ---------------- helpers ------------------------------------------------------
// tf32 MMA reads only the top 19 bits of the 32-bit container -> feeding raw
// fp32 bits == round-toward-zero tf32. No cvt needed in hot paths.
__device__ __forceinline__ uint32_t f2r(float x) { return __float_as_uint(x); }

__device__ __forceinline__ void mma_tf32(float* d, const uint32_t* a,
                                         const uint32_t* b) {
    asm volatile(
        "mma.sync.aligned.m16n8k8.row.col.f32.tf32.tf32.f32 "
        "{%0,%1,%2,%3}, {%4,%5,%6,%7}, {%8,%9}, {%0,%1,%2,%3};"
        : "+f"(d[0]), "+f"(d[1]), "+f"(d[2]), "+f"(d[3])
        : "r"(a[0]), "r"(a[1]), "r"(a[2]), "r"(a[3]), "r"(b[0]), "r"(b[1]));
}

// ---- fragment-major smem addressing (GEMM kernel) ----
__device__ __forceinline__ int a_word(int row, int k) {
    int ld = ((row & 7) << 2) | (k & 3);
    int e  = ((k & 4) >> 1) | ((row & 8) >> 3);
    int f  = ld ^ (ld >> 3);
    return (((k >> 3) << 3) | (row >> 4)) * 128 + f * 4 + e;
}
__device__ __forceinline__ int b_word(int row, int k) {
    int ld = ((row & 7) << 2) | (k & 3);
    int e  = (k & 4) >> 2;
    int h  = ld ^ (ld >> 3);
    return ((k >> 3) * 16 + (row >> 3)) * 72 + h * 2 + e;
}

// ---------------- HMMA GEMM: C = A[M,K] @ W[N,K]^T (+bias)(+relu) -------------
// 128x128 tile, BK=16, 256 threads (8 warps 4x2), warp tile 32x64,
// register-prefetch double buffer (R8 structure), raw-bit tf32 operands.
template<bool BIAS, bool RELU>
__global__ void __launch_bounds__(256, 2) gemm_mma(
    const float* __restrict__ A, const float* __restrict__ W,
    const float* __restrict__ bias, float* __restrict__ C,
    int M, int K, int ldc)
{
    constexpr int BK = 16;
    __shared__ uint32_t sAh[2][2048];
    __shared__ uint32_t sWh[2][2304];

    const int t    = threadIdx.x;
    const int m0   = blockIdx.y * 128;
    const int n0   = blockIdx.x * 128;
    const int lane = t & 31;
    const int w    = t >> 5;
    const int g    = lane >> 2;
    const int t4   = lane & 3;
    const int wm   = (w >> 1) * 32;
    const int wn   = (w & 1) * 64;
    const int mt0  = (w >> 1) * 2;
    const int nt0  = (w & 1) * 8;
    const int fl   = lane ^ (lane >> 3);
    const int lrow = t >> 1;
    const int lkq  = (t & 1) * 8;

    const float* Ap = A + (size_t)(m0 + lrow) * K + lkq;
    const float* Wp = W + (size_t)(n0 + lrow) * K + lkq;

    float acc[2][8][4];
    #pragma unroll
    for (int mt = 0; mt < 2; mt++)
        #pragma unroll
        for (int nt = 0; nt < 8; nt++)
            #pragma unroll
            for (int e = 0; e < 4; e++) acc[mt][nt][e] = 0.f;

    float4 pa0 = *(const float4*)Ap;
    float4 pa1 = *(const float4*)(Ap + 4);
    float4 pw0 = *(const float4*)Wp;
    float4 pw1 = *(const float4*)(Wp + 4);

    auto store_stage = [&](int bf_, float4 a0, float4 a1, float4 w0, float4 w1) {
        float va[8] = {a0.x, a0.y, a0.z, a0.w, a1.x, a1.y, a1.z, a1.w};
        float vw[8] = {w0.x, w0.y, w0.z, w0.w, w1.x, w1.y, w1.z, w1.w};
        #pragma unroll
        for (int u = 0; u < 8; u++) {
            const int k = lkq + u;
            sAh[bf_][a_word(lrow, k)] = f2r(va[u]);
            sWh[bf_][b_word(lrow, k)] = f2r(vw[u]);
        }
    };

    store_stage(0, pa0, pa1, pw0, pw1);
    __syncthreads();

    int buf = 0;
    for (int k0 = 0; k0 < K; k0 += BK) {
        const bool has_next = (k0 + BK < K);
        if (has_next) {
            pa0 = *(const float4*)(Ap + k0 + BK);
            pa1 = *(const float4*)(Ap + k0 + BK + 4);
            pw0 = *(const float4*)(Wp + k0 + BK);
            pw1 = *(const float4*)(Wp + k0 + BK + 4);
        }

        #pragma unroll
        for (int kk = 0; kk < 2; kk++) {
            uint4 af[2];
            uint2 bfr[8];
            #pragma unroll
            for (int mt = 0; mt < 2; mt++)
                af[mt] = *(const uint4*)&sAh[buf][(kk * 8 + mt0 + mt) * 128 + fl * 4];
            #pragma unroll
            for (int nt = 0; nt < 8; nt++)
                bfr[nt] = *(const uint2*)&sWh[buf][(kk * 16 + nt0 + nt) * 72 + fl * 2];
            #pragma unroll
            for (int mt = 0; mt < 2; mt++)
                #pragma unroll
                for (int nt = 0; nt < 8; nt++)
                    mma_tf32(acc[mt][nt], (const uint32_t*)&af[mt],
                             (const uint32_t*)&bfr[nt]);
        }

        if (has_next) {
            buf ^= 1;
            store_stage(buf, pa0, pa1, pw0, pw1);
            __syncthreads();
        }
    }

    #pragma unroll
    for (int mt = 0; mt < 2; mt++) {
        const int row = m0 + wm + mt * 16 + g;
        #pragma unroll
        for (int nt = 0; nt < 8; nt++) {
            const int col = n0 + wn + nt * 8 + 2 * t4;
            float b0v = BIAS ? bias[col]     : 0.f;
            float b1v = BIAS ? bias[col + 1] : 0.f;
            float x0 = acc[mt][nt][0] + b0v;
            float x1 = acc[mt][nt][1] + b1v;
            float x2 = acc[mt][nt][2] + b0v;
            float x3 = acc[mt][nt][3] + b1v;
            if (RELU) {
                x0 = fmaxf(x0, 0.f); x1 = fmaxf(x1, 0.f);
                x2 = fmaxf(x2, 0.f); x3 = fmaxf(x3, 0.f);
            }
            *(float2*)&C[(size_t)row * ldc + col]       = make_float2(x0, x1);
            *(float2*)&C[(size_t)(row + 8) * ldc + col] = make_float2(x2, x3);
        }
    }
}

// ---------------- MMA flash attention ------------------------------------------
__device__ __forceinline__ int bw8(int nn, int k) {
    int ld = ((nn & 7) << 2) | (k & 3);
    int e  = (k & 4) >> 2;
    int h  = ld ^ (ld >> 3);
    return ((k >> 3) * 8 + (nn >> 3)) * 72 + h * 2 + e;
}
__device__ __forceinline__ int bw16(int nn, int k) {
    int ld = ((nn & 7) << 2) | (k & 3);
    int e  = (k & 4) >> 2;
    int h  = ld ^ (ld >> 3);
    return ((k >> 3) * 16 + (nn >> 3)) * 72 + h * 2 + e;
}
__device__ __forceinline__ int aw4(int row, int k) {
    int ld = ((row & 7) << 2) | (k & 3);
    int e  = ((k & 4) >> 1) | ((row & 8) >> 3);
    int f  = ld ^ (ld >> 3);
    return ((k >> 3) * 4 + (row >> 4)) * 128 + f * 4 + e;
}

#define ATT_WORDS (4608 + 4608 + 9216 + 8448 + 256)
#define ATT_SMEM  (ATT_WORDS * 4)

__global__ void __launch_bounds__(256, 1) attn_mma(
    const float* __restrict__ heads, const float* __restrict__ rk,
    const float* __restrict__ rwb, const float* __restrict__ rrb,
    float* __restrict__ av)
{
    extern __shared__ uint32_t smw[];
    uint32_t* sK  = smw;
    uint32_t* sV  = sK + 4608;
    uint32_t* sB  = sV + 4608;
    float*    sBD = (float*)(sB + 9216);
    uint32_t* sP  = (uint32_t*)sBD;
    float*    red = sBD + 8448;

    const int i0   = (gridDim.x - 1 - blockIdx.x) * 64;
    const int n    = blockIdx.y;
    const int b    = blockIdx.z;
    const int t    = threadIdx.x;
    const int lane = t & 31;
    const int w    = t >> 5;
    const int wr   = w & 3;
    const int wc   = w >> 2;
    const int g    = lane >> 2;
    const int t4   = lane & 3;
    const int fl   = lane ^ (lane >> 3);

    uint32_t qw[8][4], qr[8][4];
    {
        const float* qb = heads + (size_t)(b * Q_ + i0 + wr * 16 + g) * D3 + n * DH_;
        const float* wb = rwb + n * DH_;
        const float* rb = rrb + n * DH_;
        #pragma unroll
        for (int kt = 0; kt < 8; kt++) {
            const int c0 = kt * 8 + t4, c1 = c0 + 4;
            float q00 = qb[c0], q01 = qb[c1];
            float q10 = qb[8 * D3 + c0], q11 = qb[8 * D3 + c1];
            qw[kt][0] = f2r(q00 + wb[c0]);
            qw[kt][1] = f2r(q10 + wb[c0]);
            qw[kt][2] = f2r(q01 + wb[c1]);
            qw[kt][3] = f2r(q11 + wb[c1]);
            qr[kt][0] = f2r(q00 + rb[c0]);
            qr[kt][1] = f2r(q10 + rb[c0]);
            qr[kt][2] = f2r(q01 + rb[c1]);
            qr[kt][3] = f2r(q11 + rb[c1]);
        }
    }

    float O[4][4];
    #pragma unroll
    for (int nt = 0; nt < 4; nt++)
        #pragma unroll
        for (int e = 0; e < 4; e++) O[nt][e] = 0.f;
    float m0r = -1e30f, m1r = -1e30f, l0r = 0.f, l1r = 0.f;

    const int di0 = wr * 16 + g;
    const int di1 = di0 + 8;

    for (int j0 = 0; j0 <= i0; j0 += 64) {
        __syncthreads();

        {
            const int jrow = t >> 2, d0 = (t & 3) * 16;
            const float* kp = heads + (size_t)(b * Q_ + j0 + jrow) * D3 + D_ + n * DH_ + d0;
            const float* vp = kp + D_;
            #pragma unroll
            for (int u = 0; u < 16; u += 4) {
                float4 kv = *(const float4*)(kp + u);
                float4 vv = *(const float4*)(vp + u);
                const int d = d0 + u;
                sK[bw8(jrow, d + 0)] = f2r(kv.x);
                sK[bw8(jrow, d + 1)] = f2r(kv.y);
                sK[bw8(jrow, d + 2)] = f2r(kv.z);
                sK[bw8(jrow, d + 3)] = f2r(kv.w);
                sV[bw8(d + 0, jrow)] = f2r(vv.x);
                sV[bw8(d + 1, jrow)] = f2r(vv.y);
                sV[bw8(d + 2, jrow)] = f2r(vv.z);
                sV[bw8(d + 3, jrow)] = f2r(vv.w);
            }
        }
        {
            const int lr_ = t >> 1, d0 = (t & 1) * 32;
            int grow = (Q_ - 64 - i0 + j0) + lr_;
            if (grow > Q_ - 1) grow = Q_ - 1;
            const float* rp = rk + (size_t)grow * D_ + n * DH_ + d0;
            #pragma unroll
            for (int u = 0; u < 32; u += 4) {
                float4 rv = *(const float4*)(rp + u);
                const int d = d0 + u;
                sB[bw16(lr_, d + 0)] = f2r(rv.x);
                sB[bw16(lr_, d + 1)] = f2r(rv.y);
                sB[bw16(lr_, d + 2)] = f2r(rv.z);
                sB[bw16(lr_, d + 3)] = f2r(rv.w);
            }
        }
        __syncthreads();

        {
            float bd[8][4];
            #pragma unroll
            for (int nt = 0; nt < 8; nt++)
                #pragma unroll
                for (int e = 0; e < 4; e++) bd[nt][e] = 0.f;
            #pragma unroll
            for (int kt = 0; kt < 8; kt++) {
                uint2 bf[8];
                #pragma unroll
                for (int nt = 0; nt < 8; nt++)
                    bf[nt] = *(const uint2*)&sB[(kt * 16 + wc * 8 + nt) * 72 + fl * 2];
                #pragma unroll
                for (int nt = 0; nt < 8; nt++)
                    mma_tf32(bd[nt], qr[kt], (const uint32_t*)&bf[nt]);
            }
            #pragma unroll
            for (int nt = 0; nt < 8; nt++) {
                const int lc = wc * 64 + nt * 8 + 2 * t4;
                sBD[di0 * 132 + lc]     = bd[nt][0];
                sBD[di0 * 132 + lc + 1] = bd[nt][1];
                sBD[di1 * 132 + lc]     = bd[nt][2];
                sBD[di1 * 132 + lc + 1] = bd[nt][3];
            }
        }
        __syncthreads();

        float p[4][4];
        {
            float ac[4][4];
            #pragma unroll
            for (int nt = 0; nt < 4; nt++)
                #pragma unroll
                for (int e = 0; e < 4; e++) ac[nt][e] = 0.f;
            #pragma unroll
            for (int kt = 0; kt < 8; kt++) {
                uint2 kf[4];
                #pragma unroll
                for (int nt = 0; nt < 4; nt++)
                    kf[nt] = *(const uint2*)&sK[(kt * 8 + wc * 4 + nt) * 72 + fl * 2];
                #pragma unroll
                for (int nt = 0; nt < 4; nt++)
                    mma_tf32(ac[nt], qw[kt], (const uint32_t*)&kf[nt]);
            }
            const bool diag = (j0 == i0);
            #pragma unroll
            for (int nt = 0; nt < 4; nt++) {
                const int dj = wc * 32 + nt * 8 + 2 * t4;
                float v00 = (ac[nt][0] + sBD[di0 * 132 + 63 - di0 + dj])     * 0.125f;
                float v01 = (ac[nt][1] + sBD[di0 * 132 + 63 - di0 + dj + 1]) * 0.125f;
                float v10 = (ac[nt][2] + sBD[di1 * 132 + 63 - di1 + dj])     * 0.125f;
                float v11 = (ac[nt][3] + sBD[di1 * 132 + 63 - di1 + dj + 1]) * 0.125f;
                if (diag) {
                    if (dj     > di0) v00 = -1e30f;
                    if (dj + 1 > di0) v01 = -1e30f;
                    if (dj     > di1) v10 = -1e30f;
                    if (dj + 1 > di1) v11 = -1e30f;
                }
                p[nt][0] = v00; p[nt][1] = v01; p[nt][2] = v10; p[nt][3] = v11;
            }
        }

        {
            float mx0 = -1e30f, mx1 = -1e30f;
            #pragma unroll
            for (int nt = 0; nt < 4; nt++) {
                mx0 = fmaxf(mx0, fmaxf(p[nt][0], p[nt][1]));
                mx1 = fmaxf(mx1, fmaxf(p[nt][2], p[nt][3]));
            }
            mx0 = fmaxf(mx0, __shfl_xor_sync(0xffffffffu, mx0, 1));
            mx0 = fmaxf(mx0, __shfl_xor_sync(0xffffffffu, mx0, 2));
            mx1 = fmaxf(mx1, __shfl_xor_sync(0xffffffffu, mx1, 1));
            mx1 = fmaxf(mx1, __shfl_xor_sync(0xffffffffu, mx1, 2));
            if (t4 == 0) {
                red[wc * 64 + di0] = mx0;
                red[wc * 64 + di1] = mx1;
            }
        }
        __syncthreads();

        const float mn0 = fmaxf(m0r, fmaxf(red[di0], red[64 + di0]));
        const float mn1 = fmaxf(m1r, fmaxf(red[di1], red[64 + di1]));
        const float fac0 = __expf(m0r - mn0);
        const float fac1 = __expf(m1r - mn1);
        m0r = mn0; m1r = mn1;

        {
            float s0 = 0.f, s1 = 0.f;
            #pragma unroll
            for (int nt = 0; nt < 4; nt++) {
                p[nt][0] = __expf(p[nt][0] - mn0);
                p[nt][1] = __expf(p[nt][1] - mn0);
                p[nt][2] = __expf(p[nt][2] - mn1);
                p[nt][3] = __expf(p[nt][3] - mn1);
                s0 += p[nt][0] + p[nt][1];
                s1 += p[nt][2] + p[nt][3];
            }
            s0 += __shfl_xor_sync(0xffffffffu, s0, 1);
            s0 += __shfl_xor_sync(0xffffffffu, s0, 2);
            s1 += __shfl_xor_sync(0xffffffffu, s1, 1);
            s1 += __shfl_xor_sync(0xffffffffu, s1, 2);
            if (t4 == 0) {
                red[128 + wc * 64 + di0] = s0;
                red[128 + wc * 64 + di1] = s1;
            }
        }
        __syncthreads();

        l0r = l0r * fac0 + red[128 + di0] + red[128 + 64 + di0];
        l1r = l1r * fac1 + red[128 + di1] + red[128 + 64 + di1];
        #pragma unroll
        for (int nt = 0; nt < 4; nt++) {
            O[nt][0] *= fac0; O[nt][1] *= fac0;
            O[nt][2] *= fac1; O[nt][3] *= fac1;
        }

        #pragma unroll
        for (int nt = 0; nt < 4; nt++) {
            const int dj = wc * 32 + nt * 8 + 2 * t4;
            sP[aw4(di0, dj)]     = f2r(p[nt][0]);
            sP[aw4(di0, dj + 1)] = f2r(p[nt][1]);
            sP[aw4(di1, dj)]     = f2r(p[nt][2]);
            sP[aw4(di1, dj + 1)] = f2r(p[nt][3]);
        }
        __syncthreads();

        #pragma unroll
        for (int kt = 0; kt < 8; kt++) {
            uint4 af = *(const uint4*)&sP[(kt * 4 + wr) * 128 + fl * 4];
            uint2 vf[4];
            #pragma unroll
            for (int nt = 0; nt < 4; nt++)
                vf[nt] = *(const uint2*)&sV[(kt * 8 + wc * 4 + nt) * 72 + fl * 2];
            #pragma unroll
            for (int nt = 0; nt < 4; nt++)
                mma_tf32(O[nt], (const uint32_t*)&af, (const uint32_t*)&vf[nt]);
        }
    }

    const float inv0 = 1.f / l0r;
    const float inv1 = 1.f / l1r;
    #pragma unroll
    for (int nt = 0; nt < 4; nt++) {
        const int col = n * DH_ + wc * 32 + nt * 8 + 2 * t4;
        *(float2*)&av[(size_t)(b * Q_ + i0 + di0) * D_ + col] =
            make_float2(O[nt][0] * inv0, O[nt][1] * inv0);
        *(float2*)&av[(size_t)(b * Q_ + i0 + di1) * D_ + col] =
            make_float2(O[nt][2] * inv1, O[nt][3] * inv1);
    }
}

// ---------------- fused residual add + LayerNorm (shuffle reductions) ---------
__global__ void __launch_bounds__(256) add_ln_kernel(
    const float* __restrict__ x, const float* __restrict__ resid,
    const float* __restrict__ g, const float* __restrict__ bta,
    float* __restrict__ out)
{
    const int row = blockIdx.x;
    const int t = threadIdx.x;
    const int lane = t & 31;
    const int wid = t >> 5;
    __shared__ float red[8];
    __shared__ float bcast[2];

    float v[4];
    float s = 0.f;
    #pragma unroll
    for (int u = 0; u < 4; u++) {
        int c = t + u * 256;
        v[u] = x[(size_t)row * D_ + c] + resid[(size_t)row * D_ + c];
        s += v[u];
    }
    #pragma unroll
    for (int o = 16; o > 0; o >>= 1) s += __shfl_xor_sync(0xffffffffu, s, o);
    if (lane == 0) red[wid] = s;
    __syncthreads();
    if (t == 0) {
        float acc = 0.f;
        #pragma unroll
        for (int i = 0; i < 8; i++) acc += red[i];
        bcast[0] = acc * (1.f / D_);
    }
    __syncthreads();
    const float mean = bcast[0];

    s = 0.f;
    #pragma unroll
    for (int u = 0; u < 4; u++) {
        float dd = v[u] - mean;
        s += dd * dd;
    }
    #pragma unroll
    for (int o = 16; o > 0; o >>= 1) s += __shfl_xor_sync(0xffffffffu, s, o);
    if (lane == 0) red[wid] = s;
    __syncthreads();
    if (t == 0) {
        float acc = 0.f;
        #pragma unroll
        for (int i = 0; i < 8; i++) acc += red[i];
        bcast[1] = rsqrtf(acc * (1.f / D_) + 1e-5f);
    }
    __syncthreads();
    const float rstd = bcast[1];

    #pragma unroll
    for (int u = 0; u < 4; u++) {
        int c = t + u * 256;
        out[(size_t)row * D_ + c] = (v[u] - mean) * rstd * g[c] + bta[c];
    }
}

// ---------------- host launch -------------------------------------------------
extern "C" void kernel_launch(void* const* d_in, const int* in_sizes, int n_in,
                              void* d_out, int out_size)
{
    const float* w     = (const float*)d_in[0];
    const float* r     = (const float*)d_in[1];
    const float* qkv_w = (const float*)d_in[3];
    const float* r_w   = (const float*)d_in[4];
    const float* o_w   = (const float*)d_in[5];
    const float* rwb   = (const float*)d_in[6];
    const float* rrb   = (const float*)d_in[7];
    const float* ln1_g = (const float*)d_in[8];
    const float* ln1_b = (const float*)d_in[9];
    const float* ff_w1 = (const float*)d_in[10];
    const float* ff_b1 = (const float*)d_in[11];
    const float* ff_w2 = (const float*)d_in[12];
    const float* ff_b2 = (const float*)d_in[13];
    const float* ln2_g = (const float*)d_in[14];
    const float* ln2_b = (const float*)d_in[15];
    float* out = (float*)d_out;

    float *heads, *rk, *av, *tmp, *out1, *ff1;
    cudaGetSymbolAddress((void**)&heads, g_heads);
    cudaGetSymbolAddress((void**)&rk,    g_rk);
    cudaGetSymbolAddress((void**)&av,    g_av);
    cudaGetSymbolAddress((void**)&tmp,   g_tmp);
    cudaGetSymbolAddress((void**)&out1,  g_out1);
    cudaGetSymbolAddress((void**)&ff1,   g_ff1);

    cudaFuncSetAttribute(attn_mma,
        cudaFuncAttributeMaxDynamicSharedMemorySize, ATT_SMEM);

    // 1) QKV projection                                   [4096, 3072]
    gemm_mma<false, false><<<dim3(D3 / 128, BQ / 128), 256>>>(
        w, qkv_w, nullptr, heads, BQ, D_, D3);

    // 2) rk = r @ r_w^T                                   [1024, 1024]
    gemm_mma<false, false><<<dim3(D_ / 128, Q_ / 128), 256>>>(
        r, r_w, nullptr, rk, Q_, D_, D_);

    // 3) MMA flash attention                              av [4096, 1024]
    attn_mma<<<dim3(Q_ / 64, N_, B_), 256, ATT_SMEM>>>(
        heads, rk, rwb, rrb, av);

    // 4) O projection                                     [4096, 1024]
    gemm_mma<false, false><<<dim3(D_ / 128, BQ / 128), 256>>>(
        av, o_w, nullptr, tmp, BQ, D_, D_);

    // 5) out1 = LN(w + tmp)
    add_ln_kernel<<<BQ, 256>>>(tmp, w, ln1_g, ln1_b, out1);

    // 6) ff1 = relu(out1 @ ff_w1^T + b1)                  [4096, 4096]
    gemm_mma<true, true><<<dim3(DI_ / 128, BQ / 128), 256>>>(
        out1, ff_w1, ff_b1, ff1, BQ, D_, DI_);

    // 7) tmp = ff1 @ ff_w2^T + b2                         [4096, 1024]
    gemm_mma<true, false><<<dim3(D_ / 128, BQ / 128), 256>>>(
        ff1, ff_w2, ff_b2, tmp, BQ, DI_, D_);

    // 8) out = LN(out1 + tmp)
    add_ln_kernel<<<BQ, 256>>>(tmp, out1, ln2_g, ln2_b, out);
}